// round 2
// baseline (speedup 1.0000x reference)
#include <cuda_runtime.h>
#include <math.h>

// Problem: ArcFace loss. B=512 rows, F=128, C=100000 classes.
// d_in[0]: features [B,F] f32 row-major
// d_in[1]: w        [F,C] f32 row-major
// d_in[2]: target   [B]   int32 OR int64 (JAX x64-disabled silently gives i32;
//                         we sniff the layout at runtime, safely in-bounds)
// d_out  : scalar f32 loss

#define BB 512   // batch rows (fixed)
#define FF 128   // feature dim (fixed)
#define BM 128   // GEMM tile rows
#define BN 128   // GEMM tile cols
#define KB 32    // k chunk
#define MAX_TILES 1024

// ---------------- scratch (no allocations allowed) ----------------
__device__ float g_part[MAX_TILES * BB];  // per-(ctile,row) partial exp-sums
__device__ float g_margin[BB];            // margin logit at target (== log(top))
__device__ float g_adj[BB];               // top - exp(logit_target)

// ---------------- fast exp: FMA-only, avoids MUFU bottleneck -------
// exp(x) = 2^(x*log2e); n = rint(z), f = z-n in [-0.5,0.5]; 2^f via deg-6 poly.
// rel err ~1.2e-7 over the range seen here.
__device__ __forceinline__ float fast_exp(float x) {
    const float LOG2E = 1.4426950408889634f;
    float z = x * LOG2E;
    float n = rintf(z);
    float f = z - n;
    float p = 1.5403530393381606e-4f;
    p = fmaf(p, f, 1.3333558146428443e-3f);
    p = fmaf(p, f, 9.6181291076284770e-3f);
    p = fmaf(p, f, 5.5504108664821580e-2f);
    p = fmaf(p, f, 2.4022650695910070e-1f);
    p = fmaf(p, f, 6.9314718055994530e-1f);
    p = fmaf(p, f, 1.0f);
    int ni = (int)n;
    return __int_as_float(__float_as_int(p) + (ni << 23));
}

// Safe target fetch: works whether the buffer holds int32 or int64 values.
// Reads only the first 512 int32 words for detection (in-bounds either way:
// 512*i32 = 2048B <= min(2048B, 4096B)).
__device__ __forceinline__ int load_target(const void* tptr, int b, int C) {
    const int* p = (const int*)tptr;
    // int64 little-endian: odd words are high halves of values < 2^31 -> 0.
    bool is64 = ((p[1] | p[3] | p[5] | p[7] | p[9]) == 0);
    long long t;
    if (is64) t = ((const long long*)tptr)[b];
    else      t = (long long)p[b];
    if (t < 0) t = 0;
    if (t >= C) t = C - 1;
    return (int)t;
}

// ---------------- kernel 1: per-row aux (target column only) -------
__global__ void aux_kernel(const float* __restrict__ feat,
                           const float* __restrict__ w,
                           const void* __restrict__ target,
                           int C) {
    int b = blockIdx.x;      // 0..511
    int f = threadIdx.x;     // 0..127
    int t = load_target(target, b, C);
    float fv = feat[b * FF + f];
    float wv = w[(size_t)f * (size_t)C + (size_t)t];
    float fsq = fv * fv;
    float wsq = wv * wv;
    float dot = fv * wv;

    const unsigned m = 0xffffffffu;
    #pragma unroll
    for (int o = 16; o > 0; o >>= 1) {
        fsq += __shfl_down_sync(m, fsq, o);
        wsq += __shfl_down_sync(m, wsq, o);
        dot += __shfl_down_sync(m, dot, o);
    }
    __shared__ float s0[4], s1[4], s2[4];
    int wid = threadIdx.x >> 5;
    if ((threadIdx.x & 31) == 0) { s0[wid] = fsq; s1[wid] = wsq; s2[wid] = dot; }
    __syncthreads();
    if (threadIdx.x == 0) {
        float F2 = (s0[0] + s0[1]) + (s0[2] + s0[3]);
        float W2 = (s1[0] + s1[1]) + (s1[2] + s1[3]);
        float D  = (s2[0] + s2[1]) + (s2[2] + s2[3]);
        float modulus = sqrtf(F2) * sqrtf(W2);
        float ct = D / (modulus * 1.01f);
        ct = fminf(1.0f, fmaxf(-1.0f, ct));
        float theta = acosf(ct) + 0.5f;           // ANGLE = 0.5
        float ml = modulus * cosf(theta);          // margin logit
        g_margin[b] = ml;                          // log(top)
        g_adj[b] = expf(ml) - expf(D);             // top - exp(logit_t)
    }
}

// ---------------- kernel 2: GEMM + exp-sum epilogue ----------------
// grid = (NT, 4), block = 256 (16x16), per-thread 8x8 register tile.
__global__ void __launch_bounds__(256, 2)
gemm_expsum_kernel(const float* __restrict__ feat,
                   const float* __restrict__ w,
                   int C) {
    __shared__ float As[KB][BM];       // [k][m], transposed for vector LDS
    __shared__ float Bs[KB][BN];       // [k][c]
    __shared__ float red[BM][17];      // row-sum reduce buffer (padded)

    const int tid = threadIdx.x;
    const int tx = tid & 15;           // col group
    const int ty = tid >> 4;           // row group
    const int m0 = blockIdx.y * BM;
    const int c0 = blockIdx.x * BN;

    float acc[8][8];
    #pragma unroll
    for (int i = 0; i < 8; i++)
        #pragma unroll
        for (int j = 0; j < 8; j++) acc[i][j] = 0.0f;

    for (int k0 = 0; k0 < FF; k0 += KB) {
        // load A chunk: BM x KB floats = 1024 float4, 4 per thread
        #pragma unroll
        for (int i = 0; i < 4; i++) {
            int idx = i * 256 + tid;           // 0..1023
            int mm = idx >> 3;                 // row 0..127
            int kg = idx & 7;                  // k-group (4 floats)
            float4 v = *(const float4*)&feat[(m0 + mm) * FF + k0 + kg * 4];
            As[kg * 4 + 0][mm] = v.x;
            As[kg * 4 + 1][mm] = v.y;
            As[kg * 4 + 2][mm] = v.z;
            As[kg * 4 + 3][mm] = v.w;
        }
        // load B chunk: KB x BN floats = 1024 float4, 4 per thread
        #pragma unroll
        for (int i = 0; i < 4; i++) {
            int idx = i * 256 + tid;           // 0..1023
            int kk = idx >> 5;                 // k row 0..31
            int cg = idx & 31;                 // col group
            int c = c0 + cg * 4;
            float4 v;
            if (c < C) {                       // C % 4 == 0 so all-or-nothing
                v = *(const float4*)&w[(size_t)(k0 + kk) * (size_t)C + c];
            } else {
                v = make_float4(0.f, 0.f, 0.f, 0.f);
            }
            *(float4*)&Bs[kk][cg * 4] = v;
        }
        __syncthreads();

        #pragma unroll 8
        for (int kk = 0; kk < KB; kk++) {
            float4 a0 = *(const float4*)&As[kk][ty * 8];
            float4 a1 = *(const float4*)&As[kk][ty * 8 + 4];
            float4 b0 = *(const float4*)&Bs[kk][tx * 8];
            float4 b1 = *(const float4*)&Bs[kk][tx * 8 + 4];
            float a[8] = {a0.x, a0.y, a0.z, a0.w, a1.x, a1.y, a1.z, a1.w};
            float bb[8] = {b0.x, b0.y, b0.z, b0.w, b1.x, b1.y, b1.z, b1.w};
            #pragma unroll
            for (int i = 0; i < 8; i++)
                #pragma unroll
                for (int j = 0; j < 8; j++)
                    acc[i][j] = fmaf(a[i], bb[j], acc[i][j]);
        }
        __syncthreads();
    }

    // epilogue: exp + per-row sum over this thread's 8 cols
    #pragma unroll
    for (int i = 0; i < 8; i++) {
        float rs = 0.0f;
        #pragma unroll
        for (int j = 0; j < 8; j++) {
            int c = c0 + tx * 8 + j;
            float e = fast_exp(acc[i][j]);
            if (c < C) rs += e;
        }
        red[ty * 8 + i][tx] = rs;
    }
    __syncthreads();
    // 128 threads: fixed-order reduce across the 16 col-groups (deterministic)
    if (tid < BM) {
        float s = 0.0f;
        #pragma unroll
        for (int t = 0; t < 16; t++) s += red[tid][t];
        g_part[blockIdx.x * BB + m0 + tid] = s;
    }
}

// ---------------- kernel 3: finalize ----------------
__global__ void finalize_kernel(int NT, float* __restrict__ out) {
    int b = threadIdx.x;  // 0..511
    float s0 = 0.f, s1 = 0.f, s2 = 0.f, s3 = 0.f;
    int t = 0;
    for (; t + 4 <= NT; t += 4) {
        s0 += g_part[(t + 0) * BB + b];
        s1 += g_part[(t + 1) * BB + b];
        s2 += g_part[(t + 2) * BB + b];
        s3 += g_part[(t + 3) * BB + b];
    }
    for (; t < NT; t++) s0 += g_part[t * BB + b];
    float S = (s0 + s1) + (s2 + s3);
    float down = S + g_adj[b];
    float v = logf(down) - g_margin[b];   // -log(top/down)

    __shared__ float red[BB];
    red[b] = v;
    __syncthreads();
    #pragma unroll
    for (int o = BB / 2; o > 0; o >>= 1) {
        if (b < o) red[b] += red[b + o];
        __syncthreads();
    }
    if (b == 0) out[0] = red[0] / (float)BB;
}

// ---------------- launch ----------------
extern "C" void kernel_launch(void* const* d_in, const int* in_sizes, int n_in,
                              void* d_out, int out_size) {
    const float* feat = (const float*)d_in[0];
    const float* w    = (const float*)d_in[1];
    const void*  target = d_in[2];
    float* out = (float*)d_out;

    int C  = in_sizes[1] / FF;               // 100000
    int NT = (C + BN - 1) / BN;              // 782

    aux_kernel<<<BB, FF>>>(feat, w, target, C);
    gemm_expsum_kernel<<<dim3(NT, BB / BM), 256>>>(feat, w, C);
    finalize_kernel<<<1, BB>>>(NT, out);
}

// round 4
// speedup vs baseline: 2.5644x; 2.5644x over previous
#include <cuda_runtime.h>
#include <cuda_bf16.h>
#include <math.h>
#include <stdint.h>

// ArcFace loss. B=512, F=128, C=100000.
// d_in[0]: features [512,128] f32   d_in[1]: w [128,100000] f32
// d_in[2]: target [512] i32-or-i64 (sniffed)   d_out: scalar f32
//
// tcgen05 is ptxas-rejected (module target is plain sm_103), so the GEMM uses
// portable mma.sync.m16n8k16 bf16 + ldmatrix. Block 0 of the fused kernel does
// the exact-fp32 target-column math; blocks 1..NT do GEMM+exp-sum; two tiny
// deterministic finalize kernels produce the scalar.

#define FF 128
#define BB 512
#define BN 256          // N-tile per CTA
#define NTILES 391      // ceil(100000/256)
#define PADC 96.0f      // padded cols in last tile (exp(0)=1 each)

__device__ float g_part[BB * 512];   // [row][tile] (tile slot padded to 512)
__device__ float g_margin[BB];
__device__ float g_adj[BB];
__device__ float g_rowv[BB];

// ---- smem layout (bytes). Row stride 272B (=136 bf16) -> conflict-free ldmatrix.
#define SM_B     0                    // 256 x 272          = 69632
#define SM_A     69632                // 2 bufs x 64 x 272  = 34816
#define SM_RED   104448               // 64*4 floats        = 1024
#define SM_TOTAL 105472

__device__ __forceinline__ uint32_t smem_u32(const void* p) {
    uint32_t a;
    asm("{ .reg .u64 t; cvta.to.shared.u64 t, %1; cvt.u32.u64 %0, t; }"
        : "=r"(a) : "l"(p));
    return a;
}
__device__ __forceinline__ void ldsm4(uint32_t* r, uint32_t addr) {
    asm volatile("ldmatrix.sync.aligned.m8n8.x4.shared.b16 {%0,%1,%2,%3}, [%4];"
                 : "=r"(r[0]), "=r"(r[1]), "=r"(r[2]), "=r"(r[3]) : "r"(addr));
}
__device__ __forceinline__ void mma_bf16(float* d, const uint32_t* a,
                                         uint32_t b0, uint32_t b1) {
    asm volatile(
        "mma.sync.aligned.m16n8k16.row.col.f32.bf16.bf16.f32 "
        "{%0,%1,%2,%3}, {%4,%5,%6,%7}, {%8,%9}, {%0,%1,%2,%3};"
        : "+f"(d[0]), "+f"(d[1]), "+f"(d[2]), "+f"(d[3])
        : "r"(a[0]), "r"(a[1]), "r"(a[2]), "r"(a[3]), "r"(b0), "r"(b1));
}
__device__ __forceinline__ uint32_t pack_bf16x2(float lo, float hi) {
    __nv_bfloat162 p = __floats2bfloat162_rn(lo, hi);
    return *(uint32_t*)&p;
}

// Safe target fetch: int32 vs int64 sniff (reads in-bounds either way).
__device__ __forceinline__ int load_target(const void* tptr, int b, int C) {
    const int* p = (const int*)tptr;
    bool is64 = ((p[1] | p[3] | p[5] | p[7] | p[9]) == 0);
    long long t = is64 ? ((const long long*)tptr)[b] : (long long)p[b];
    if (t < 0) t = 0;
    if (t >= C) t = C - 1;
    return (int)t;
}

// ================= fused kernel =================
__global__ void __launch_bounds__(256, 2)
fused_kernel(const float* __restrict__ feat, const float* __restrict__ w,
             const void* __restrict__ target, int C, int NT) {
    extern __shared__ char smem[];
    const int tid  = threadIdx.x;
    const int wid  = tid >> 5;
    const int lane = tid & 31;

    // ---------------- block 0: aux + zero-pad of g_part ----------------
    if (blockIdx.x == 0) {
        // zero unused tile slots [NT..511] of every row (read by finalize1)
        int padn = 512 - NT;
        for (int idx = tid; idx < BB * padn; idx += 256) {
            int r = idx / padn, t = NT + idx % padn;
            g_part[r * 512 + t] = 0.0f;
        }
        // target-column fp32 math: warp per row, 64 rows per warp
        for (int it = 0; it < 64; it++) {
            int b = it * 8 + wid;
            int t = load_target(target, b, C);
            float fsq = 0.f, wsq = 0.f, dot = 0.f;
            #pragma unroll
            for (int q = 0; q < 4; q++) {
                int f = lane + q * 32;
                float fv = feat[b * FF + f];
                float wv = w[(size_t)f * (size_t)C + (size_t)t];
                fsq = fmaf(fv, fv, fsq);
                wsq = fmaf(wv, wv, wsq);
                dot = fmaf(fv, wv, dot);
            }
            const unsigned msk = 0xffffffffu;
            #pragma unroll
            for (int o = 16; o > 0; o >>= 1) {
                fsq += __shfl_down_sync(msk, fsq, o);
                wsq += __shfl_down_sync(msk, wsq, o);
                dot += __shfl_down_sync(msk, dot, o);
            }
            if (lane == 0) {
                float modulus = sqrtf(fsq) * sqrtf(wsq);
                float ct = dot / (modulus * 1.01f);
                ct = fminf(1.0f, fmaxf(-1.0f, ct));
                float ml = modulus * cosf(acosf(ct) + 0.5f);  // ANGLE=0.5
                g_margin[b] = ml;
                g_adj[b] = expf(ml) - expf(dot);
            }
        }
        return;
    }

    // ---------------- GEMM blocks ----------------
    const int bx = blockIdx.x - 1;        // tile index 0..NT-1
    const int c0 = bx * BN;
    const uint32_t sb = smem_u32(smem);
    const int wm = wid & 1;               // warp row half (32 rows)
    const int wn = wid >> 1;              // warp col quarter (64 cols)

    // ---- load B tile: w[k][c0+n] -> bs[n][k] bf16, rows padded to 272B ----
    {
        const float4* w4 = (const float4*)w;
        #pragma unroll
        for (int i = 0; i < 16; i++) {
            int idx = i * 256 + tid;      // 0..4095
            int kp = idx >> 6;            // k pair 0..63
            int cq = idx & 63;            // col quad
            int k = kp * 2, c = c0 + cq * 4;
            float4 v0 = make_float4(0.f, 0.f, 0.f, 0.f), v1 = v0;
            if (c < C) {                  // C % 4 == 0 -> all-or-nothing
                v0 = w4[((size_t)k * (size_t)C + (size_t)c) >> 2];
                v1 = w4[((size_t)(k + 1) * (size_t)C + (size_t)c) >> 2];
            }
            float a0[4] = {v0.x, v0.y, v0.z, v0.w};
            float a1[4] = {v1.x, v1.y, v1.z, v1.w};
            #pragma unroll
            for (int j = 0; j < 4; j++) {
                int n = cq * 4 + j;
                *(uint32_t*)(smem + SM_B + n * 272 + k * 2) = pack_bf16x2(a0[j], a1[j]);
            }
        }
    }
    // ---- load A m-tile 0 (rows 0..63) ----
    {
        const float4* f4 = (const float4*)feat;
        #pragma unroll
        for (int i = 0; i < 8; i++) {
            int idx = i * 256 + tid;      // 0..2047
            int r = idx >> 5, kq = idx & 31;
            float4 v = f4[r * 32 + kq];
            uint2 pk;
            pk.x = pack_bf16x2(v.x, v.y);
            pk.y = pack_bf16x2(v.z, v.w);
            *(uint2*)(smem + SM_A + r * 272 + kq * 8) = pk;
        }
    }
    __syncthreads();

    // per-lane ldmatrix base addresses
    // A: row = wm*32 + mi*16 + (lane&15), col halves by lane>>4
    uint32_t a_lb = (uint32_t)((wm * 32 + (lane & 15)) * 272 + ((lane >> 4) << 4));
    // B: n = wn*64 + np*16 + ((lane>>4)<<3) + (lane&7), k half by (lane>>3)&1
    uint32_t b_lb[4];
    #pragma unroll
    for (int np = 0; np < 4; np++) {
        int n = wn * 64 + np * 16 + ((lane >> 4) << 3) + (lane & 7);
        b_lb[np] = sb + SM_B + (uint32_t)(n * 272 + (((lane >> 3) & 1) << 4));
    }
    float* red = (float*)(smem + SM_RED);

    for (int m = 0; m < 8; m++) {
        const uint32_t abase = sb + SM_A + (m & 1) * 17408;

        // prefetch next A m-tile into the other buffer (visible after the
        // __syncthreads() at the end of this iteration)
        if (m < 7) {
            const float4* f4 = (const float4*)feat;
            char* dst = smem + SM_A + ((m + 1) & 1) * 17408;
            int m0 = (m + 1) * 64;
            #pragma unroll
            for (int i = 0; i < 8; i++) {
                int idx = i * 256 + tid;
                int r = idx >> 5, kq = idx & 31;
                float4 v = f4[(m0 + r) * 32 + kq];
                uint2 pk;
                pk.x = pack_bf16x2(v.x, v.y);
                pk.y = pack_bf16x2(v.z, v.w);
                *(uint2*)(dst + r * 272 + kq * 8) = pk;
            }
        }

        float acc[2][8][4];
        #pragma unroll
        for (int mi = 0; mi < 2; mi++)
            #pragma unroll
            for (int j = 0; j < 8; j++)
                #pragma unroll
                for (int q = 0; q < 4; q++) acc[mi][j][q] = 0.0f;

        #pragma unroll
        for (int ks = 0; ks < 8; ks++) {
            uint32_t a[2][4];
            ldsm4(a[0], abase + a_lb + ks * 32);
            ldsm4(a[1], abase + a_lb + 16 * 272 + ks * 32);
            #pragma unroll
            for (int np = 0; np < 4; np++) {
                uint32_t bfr[4];
                ldsm4(bfr, b_lb[np] + ks * 32);
                #pragma unroll
                for (int mi = 0; mi < 2; mi++) {
                    mma_bf16(acc[mi][np * 2 + 0], a[mi], bfr[0], bfr[1]);
                    mma_bf16(acc[mi][np * 2 + 1], a[mi], bfr[2], bfr[3]);
                }
            }
        }

        // epilogue: exp + row sums (deterministic)
        const unsigned msk = 0xffffffffu;
        #pragma unroll
        for (int mi = 0; mi < 2; mi++) {
            float s0 = 0.f, s1 = 0.f;
            #pragma unroll
            for (int j = 0; j < 8; j++) {
                s0 += __expf(acc[mi][j][0]);
                s0 += __expf(acc[mi][j][1]);
                s1 += __expf(acc[mi][j][2]);
                s1 += __expf(acc[mi][j][3]);
            }
            s0 += __shfl_xor_sync(msk, s0, 1);
            s0 += __shfl_xor_sync(msk, s0, 2);
            s1 += __shfl_xor_sync(msk, s1, 1);
            s1 += __shfl_xor_sync(msk, s1, 2);
            if ((lane & 3) == 0) {
                int g = lane >> 2;
                red[(wm * 32 + mi * 16 + g) * 4 + wn] = s0;
                red[(wm * 32 + mi * 16 + g + 8) * 4 + wn] = s1;
            }
        }
        __syncthreads();
        if (tid < 64) {
            float s = (red[tid * 4 + 0] + red[tid * 4 + 1])
                    + (red[tid * 4 + 2] + red[tid * 4 + 3]);
            g_part[(m * 64 + tid) * 512 + bx] = s;
        }
        __syncthreads();
    }
}

// ================= finalize 1: per-row value =================
__global__ void finalize1_kernel(float* __restrict__ dummy) {
    int row = blockIdx.x;        // 0..511
    int j = threadIdx.x;         // 0..127
    const float* p = &g_part[row * 512];
    float s = ((p[j] + p[j + 128]) + (p[j + 256] + p[j + 384]));
    __shared__ float red[128];
    red[j] = s;
    __syncthreads();
    #pragma unroll
    for (int o = 64; o > 0; o >>= 1) {
        if (j < o) red[j] += red[j + o];
        __syncthreads();
    }
    if (j == 0) {
        float down = red[0] - PADC + g_adj[row];
        g_rowv[row] = logf(down) - g_margin[row];
    }
}

// ================= finalize 2: scalar =================
__global__ void finalize2_kernel(float* __restrict__ out) {
    int b = threadIdx.x;         // 0..511
    __shared__ float red[BB];
    red[b] = g_rowv[b];
    __syncthreads();
    #pragma unroll
    for (int o = BB / 2; o > 0; o >>= 1) {
        if (b < o) red[b] += red[b + o];
        __syncthreads();
    }
    if (b == 0) out[0] = red[0] / (float)BB;
}

// ================= launch =================
extern "C" void kernel_launch(void* const* d_in, const int* in_sizes, int n_in,
                              void* d_out, int out_size) {
    const float* feat = (const float*)d_in[0];
    const float* w    = (const float*)d_in[1];
    const void*  target = d_in[2];
    float* out = (float*)d_out;

    int C  = in_sizes[1] / FF;               // 100000
    int NT = (C + BN - 1) / BN;              // 391

    cudaFuncSetAttribute(fused_kernel,
                         cudaFuncAttributeMaxDynamicSharedMemorySize, SM_TOTAL);

    fused_kernel<<<NT + 1, 256, SM_TOTAL>>>(feat, w, target, C, NT);
    finalize1_kernel<<<BB, 128>>>(out);
    finalize2_kernel<<<1, BB>>>(out);
}

// round 5
// speedup vs baseline: 4.6264x; 1.8041x over previous
#include <cuda_runtime.h>
#include <cuda_bf16.h>
#include <math.h>
#include <stdint.h>

// ArcFace loss. B=512, F=128, C=100000.
// Persistent-CTA bf16 mma.sync GEMM + exp-sum with double-buffered B so DRAM
// streaming of w overlaps MMA. d_in[2] target is i32-or-i64 (sniffed).

#define FF 128
#define BB 512
#define BN 256
#define NCTA 148

__device__ float g_part[512 * BB];   // [tile][row]
__device__ float g_margin[BB];
__device__ float g_adj[BB];
__device__ float g_rowv[BB];

// smem: B 2x(128 rows x 528B) | A 2x(128 rows x 272B) | red 128x4 f32
#define BSTRIDE 528
#define BSZ     (128 * BSTRIDE)      // 67584
#define ASTRIDE 272
#define ASZ     (128 * ASTRIDE)      // 34816
#define SM_B    0
#define SM_A    (2 * BSZ)            // 135168
#define SM_RED  (SM_A + 2 * ASZ)     // 204800
#define SM_TOTAL (SM_RED + 2048)     // 206848

__device__ __forceinline__ uint32_t smem_u32(const void* p) {
    uint32_t a;
    asm("{ .reg .u64 t; cvta.to.shared.u64 t, %1; cvt.u32.u64 %0, t; }"
        : "=r"(a) : "l"(p));
    return a;
}
__device__ __forceinline__ void ldsm4(uint32_t* r, uint32_t addr) {
    asm volatile("ldmatrix.sync.aligned.m8n8.x4.shared.b16 {%0,%1,%2,%3}, [%4];"
                 : "=r"(r[0]), "=r"(r[1]), "=r"(r[2]), "=r"(r[3]) : "r"(addr));
}
__device__ __forceinline__ void ldsm4t(uint32_t* r, uint32_t addr) {
    asm volatile("ldmatrix.sync.aligned.m8n8.x4.trans.shared.b16 {%0,%1,%2,%3}, [%4];"
                 : "=r"(r[0]), "=r"(r[1]), "=r"(r[2]), "=r"(r[3]) : "r"(addr));
}
__device__ __forceinline__ void mma_bf16(float* d, const uint32_t* a,
                                         uint32_t b0, uint32_t b1) {
    asm volatile(
        "mma.sync.aligned.m16n8k16.row.col.f32.bf16.bf16.f32 "
        "{%0,%1,%2,%3}, {%4,%5,%6,%7}, {%8,%9}, {%0,%1,%2,%3};"
        : "+f"(d[0]), "+f"(d[1]), "+f"(d[2]), "+f"(d[3])
        : "r"(a[0]), "r"(a[1]), "r"(a[2]), "r"(a[3]), "r"(b0), "r"(b1));
}
__device__ __forceinline__ uint32_t pack_bf16x2(float lo, float hi) {
    __nv_bfloat162 p = __floats2bfloat162_rn(lo, hi);
    return *(uint32_t*)&p;
}
__device__ __forceinline__ float fast_exp(float x) {   // FMA-pipe exp
    float z = x * 1.4426950408889634f;
    float n = rintf(z);
    float f = z - n;
    float p = 1.5403530393381606e-4f;
    p = fmaf(p, f, 1.3333558146428443e-3f);
    p = fmaf(p, f, 9.6181291076284770e-3f);
    p = fmaf(p, f, 5.5504108664821580e-2f);
    p = fmaf(p, f, 2.4022650695910070e-1f);
    p = fmaf(p, f, 6.9314718055994530e-1f);
    p = fmaf(p, f, 1.0f);
    return __int_as_float(__float_as_int(p) + ((int)n << 23));
}
__device__ __forceinline__ int load_target(const void* tptr, int b, int C) {
    const int* p = (const int*)tptr;
    bool is64 = ((p[1] | p[3] | p[5] | p[7] | p[9]) == 0);
    long long t = is64 ? ((const long long*)tptr)[b] : (long long)p[b];
    if (t < 0) t = 0;
    if (t >= C) t = C - 1;
    return (int)t;
}

// Load 32 k-rows (chunk m) of B tile at col base c0 into buffer buf.
// Layout: [k][n] bf16, row stride 528B, 16B-chunk XOR swizzle by (k>>3)&1.
__device__ __forceinline__ void load_B_chunk(const float* __restrict__ w,
                                             char* smem, int buf, int m,
                                             int c0, int C, int tid) {
    const float4* w4 = (const float4*)w;
    char* base = smem + SM_B + buf * BSZ;
    #pragma unroll
    for (int i = 0; i < 4; i++) {
        int idx = i * 512 + tid;              // 0..2047
        int k = m * 32 + (idx >> 6);          // tile-local k row
        int cq = idx & 63;
        int c = c0 + cq * 4;
        float4 v = make_float4(0.f, 0.f, 0.f, 0.f);
        if (c < C)                            // C % 4 == 0 -> all-or-nothing
            v = w4[((size_t)k * (size_t)C + (size_t)c) >> 2];
        uint2 pk;
        pk.x = pack_bf16x2(v.x, v.y);
        pk.y = pack_bf16x2(v.z, v.w);
        uint32_t byte = (uint32_t)(cq * 8) ^ (uint32_t)(((k >> 3) & 1) << 4);
        *(uint2*)(base + k * BSTRIDE + byte) = pk;
    }
}

// Load A chunk (128 feature rows starting at chunk*128) into buffer buf.
__device__ __forceinline__ void load_A_chunk(const float* __restrict__ feat,
                                             char* smem, int buf, int chunk,
                                             int tid) {
    const float4* f4 = (const float4*)feat;
    char* base = smem + SM_A + buf * ASZ;
    #pragma unroll
    for (int i = 0; i < 8; i++) {
        int idx = i * 512 + tid;              // 0..4095
        int r = idx >> 5, kq = idx & 31;
        float4 v = f4[(chunk * 128 + r) * 32 + kq];
        uint2 pk;
        pk.x = pack_bf16x2(v.x, v.y);
        pk.y = pack_bf16x2(v.z, v.w);
        *(uint2*)(base + r * ASTRIDE + kq * 8) = pk;
    }
}

// ================= persistent fused kernel =================
__global__ void __launch_bounds__(512, 1)
fused_kernel(const float* __restrict__ feat, const float* __restrict__ w,
             const void* __restrict__ target, int C, int NT) {
    extern __shared__ char smem[];
    const int tid  = threadIdx.x;
    const int wid  = tid >> 5;
    const int lane = tid & 31;
    const int bid  = blockIdx.x;
    const int wm   = wid >> 2;            // warp row group (32 rows)
    const int wn   = wid & 3;             // warp col group (64 cols)
    const uint32_t sb = smem_u32(smem);
    float* red = (float*)(smem + SM_RED);

    const int niter = (NT - bid + NCTA - 1) / NCTA;   // tiles for this CTA

    // ---- prologue: first B tile (all 4 chunks) + A chunk 0 + aux ----
    #pragma unroll
    for (int m = 0; m < 4; m++)
        load_B_chunk(w, smem, 0, m, bid * BN, C, tid);
    load_A_chunk(feat, smem, 0, 0, tid);

    // aux: target-column exact fp32 math, rows bid*4 .. bid*4+3 (CTAs 0..127)
    if (bid < 128 && wid < 4) {
        int b = bid * 4 + wid;
        int t = load_target(target, b, C);
        float fsq = 0.f, wsq = 0.f, dot = 0.f;
        #pragma unroll
        for (int q = 0; q < 4; q++) {
            int f = lane + q * 32;
            float fv = feat[b * FF + f];
            float wv = w[(size_t)f * (size_t)C + (size_t)t];
            fsq = fmaf(fv, fv, fsq);
            wsq = fmaf(wv, wv, wsq);
            dot = fmaf(fv, wv, dot);
        }
        const unsigned msk = 0xffffffffu;
        #pragma unroll
        for (int o = 16; o > 0; o >>= 1) {
            fsq += __shfl_down_sync(msk, fsq, o);
            wsq += __shfl_down_sync(msk, wsq, o);
            dot += __shfl_down_sync(msk, dot, o);
        }
        if (lane == 0) {
            float modulus = sqrtf(fsq) * sqrtf(wsq);
            float ct = dot / (modulus * 1.01f);
            ct = fminf(1.0f, fmaxf(-1.0f, ct));
            float ml = modulus * cosf(acosf(ct) + 0.5f);  // ANGLE=0.5
            g_margin[b] = ml;
            g_adj[b] = expf(ml) - expf(dot);
        }
    }
    __syncthreads();

    // per-lane ldmatrix bases
    // A (row-major [m][k], stride 272): rows wm*32+(lane&15), k-half lane>>4
    const uint32_t a_lb = (uint32_t)((wm * 32 + (lane & 15)) * ASTRIDE
                                     + ((lane >> 4) << 4));
    // B ([k][n] stride 528, trans): f=lane>>3: k = (f&1)*8+(lane&7), n-octet f>>1
    const uint32_t b_lb = (uint32_t)((((lane >> 3) & 1) * 8 + (lane & 7)) * BSTRIDE
                          + (((uint32_t)(wn * 128 + ((lane >> 4) << 4)))
                             ^ (uint32_t)(((lane >> 3) & 1) << 4)));

    int cur = 0;
    for (int it = 0; it < niter; it++) {
        const int bx = bid + it * NCTA;
        const bool have_next = (it + 1 < niter);
        const int nc0 = (bx + NCTA) * BN;

        for (int m = 0; m < 4; m++) {
            const bool last_all = (it == niter - 1) && (m == 3);
            // prefetch next A chunk + next-tile B chunk (land behind MMA)
            if (!last_all)
                load_A_chunk(feat, smem, (m + 1) & 1, (m + 1) & 3, tid);
            if (have_next)
                load_B_chunk(w, smem, cur ^ 1, m, nc0, C, tid);

            const uint32_t abase = sb + SM_A + (m & 1) * ASZ;
            const uint32_t bbase = sb + SM_B + cur * BSZ;

            float acc[2][8][4];
            #pragma unroll
            for (int mi = 0; mi < 2; mi++)
                #pragma unroll
                for (int j = 0; j < 8; j++)
                    #pragma unroll
                    for (int q = 0; q < 4; q++) acc[mi][j][q] = 0.0f;

            #pragma unroll
            for (int ks = 0; ks < 8; ks++) {
                uint32_t a[2][4];
                ldsm4(a[0], abase + a_lb + ks * 32);
                ldsm4(a[1], abase + a_lb + 16 * ASTRIDE + ks * 32);
                #pragma unroll
                for (int np = 0; np < 4; np++) {
                    uint32_t bfr[4];
                    ldsm4t(bfr, bbase + b_lb + ks * 16 * BSTRIDE + np * 32);
                    #pragma unroll
                    for (int mi = 0; mi < 2; mi++) {
                        mma_bf16(acc[mi][np * 2 + 0], a[mi], bfr[0], bfr[1]);
                        mma_bf16(acc[mi][np * 2 + 1], a[mi], bfr[2], bfr[3]);
                    }
                }
            }

            // epilogue: exp (hybrid MUFU/FMA) + deterministic row sums
            const unsigned msk = 0xffffffffu;
            #pragma unroll
            for (int mi = 0; mi < 2; mi++) {
                float s0 = 0.f, s1 = 0.f;
                #pragma unroll
                for (int j = 0; j < 8; j++) {
                    s0 += __expf(acc[mi][j][0]);      // MUFU half
                    s0 += __expf(acc[mi][j][1]);
                    s1 += fast_exp(acc[mi][j][2]);    // FMA half
                    s1 += fast_exp(acc[mi][j][3]);
                }
                s0 += __shfl_xor_sync(msk, s0, 1);
                s0 += __shfl_xor_sync(msk, s0, 2);
                s1 += __shfl_xor_sync(msk, s1, 1);
                s1 += __shfl_xor_sync(msk, s1, 2);
                if ((lane & 3) == 0) {
                    int g = lane >> 2;
                    red[(wm * 32 + mi * 16 + g) * 4 + wn] = s0;
                    red[(wm * 32 + mi * 16 + g + 8) * 4 + wn] = s1;
                }
            }
            __syncthreads();
            if (tid < 128) {
                float s = (red[tid * 4 + 0] + red[tid * 4 + 1])
                        + (red[tid * 4 + 2] + red[tid * 4 + 3]);
                g_part[(size_t)bx * BB + m * 128 + tid] = s;
            }
            __syncthreads();
        }
        cur ^= 1;
    }
}

// ================= finalize 1: per-row value =================
__global__ void finalize1_kernel(int NT, float pad) {
    int row = blockIdx.x;        // 0..511
    int j = threadIdx.x;         // 0..127
    const float* p = g_part + row;
    float s = p[(size_t)j * BB] + p[(size_t)(j + 128) * BB]
            + p[(size_t)(j + 256) * BB];
    if (j + 384 < NT) s += p[(size_t)(j + 384) * BB];
    __shared__ float red[128];
    red[j] = s;
    __syncthreads();
    #pragma unroll
    for (int o = 64; o > 0; o >>= 1) {
        if (j < o) red[j] += red[j + o];
        __syncthreads();
    }
    if (j == 0) {
        float down = red[0] - pad + g_adj[row];
        g_rowv[row] = logf(down) - g_margin[row];
    }
}

// ================= finalize 2: scalar =================
__global__ void finalize2_kernel(float* __restrict__ out) {
    int b = threadIdx.x;         // 0..511
    __shared__ float red[BB];
    red[b] = g_rowv[b];
    __syncthreads();
    #pragma unroll
    for (int o = BB / 2; o > 0; o >>= 1) {
        if (b < o) red[b] += red[b + o];
        __syncthreads();
    }
    if (b == 0) out[0] = red[0] / (float)BB;
}

// ================= launch =================
extern "C" void kernel_launch(void* const* d_in, const int* in_sizes, int n_in,
                              void* d_out, int out_size) {
    const float* feat = (const float*)d_in[0];
    const float* w    = (const float*)d_in[1];
    const void*  target = d_in[2];
    float* out = (float*)d_out;

    int C  = in_sizes[1] / FF;               // 100000
    int NT = (C + BN - 1) / BN;              // 391
    float pad = (float)(NT * BN - C);        // 96

    cudaFuncSetAttribute(fused_kernel,
                         cudaFuncAttributeMaxDynamicSharedMemorySize, SM_TOTAL);

    fused_kernel<<<NCTA, 512, SM_TOTAL>>>(feat, w, target, C, NT);
    finalize1_kernel<<<BB, 128>>>(NT, pad);
    finalize2_kernel<<<1, BB>>>(out);
}